// round 11
// baseline (speedup 1.0000x reference)
#include <cuda_runtime.h>
#include <cstdint>

// ---------------------------------------------------------------------------
// Round 11:
//   up: warp-level WORK STEALING in 16-tile contiguous grains (fixes the
//       single-wave straggler tail that regressed round 10), keeping the
//       index prefetch pipeline + sorted-k range shortcut.
// ---------------------------------------------------------------------------

__device__ uint4 g_a[1000000 * 8];    // pooled rows: [m][0..3]=hi frags, [4..7]=lo
__device__ uint4 g_b[27 * 256];       // -W fragments: (h1,h2,l1,l2)
__device__ int   g_cursor[1000000];
__device__ __align__(16) int g_csr[32000000];   // 32-slot buckets per pooled row
__device__ int   g_tilectr;

#define GRAIN 16   // tiles per steal (16 tiles = 256 pairs, spans <=2 k values)

static __device__ __forceinline__ void red_add_v4(float* dst, float a, float b,
                                                  float c, float d) {
    asm volatile("red.global.add.v4.f32 [%0], {%1,%2,%3,%4};"
                 :: "l"(dst), "f"(a), "f"(b), "f"(c), "f"(d) : "memory");
}
static __device__ __forceinline__ uint32_t bf2(float hi, float lo) {
    uint32_t r;
    asm("cvt.rn.bf16x2.f32 %0, %1, %2;" : "=r"(r) : "f"(hi), "f"(lo));
    return r;
}
static __device__ __forceinline__ void split2(float v0, float v1,
                                              uint32_t& h, uint32_t& l) {
    h = bf2(v1, v0);
    float f0 = __uint_as_float(h << 16);
    float f1 = __uint_as_float(h & 0xFFFF0000u);
    l = bf2(v1 - f1, v0 - f0);
}
static __device__ __forceinline__ void mma_bf16(float c[4],
        uint32_t a0, uint32_t a1, uint32_t a2, uint32_t a3,
        uint32_t b0, uint32_t b1) {
    asm volatile(
        "mma.sync.aligned.m16n8k16.row.col.f32.bf16.bf16.f32 "
        "{%0,%1,%2,%3}, {%4,%5,%6,%7}, {%8,%9}, {%0,%1,%2,%3};"
        : "+f"(c[0]), "+f"(c[1]), "+f"(c[2]), "+f"(c[3])
        : "r"(a0), "r"(a1), "r"(a2), "r"(a3), "r"(b0), "r"(b1));
}

// ---- launch 1: weight-split + zero cursors/counter + out = feat - bias -----
__global__ void prep_kernel(const float* __restrict__ weight,
                            const float4* __restrict__ feat4,
                            const float4* __restrict__ bias4,
                            float4* __restrict__ out4,
                            int M, int n8, int gw, int gz) {
    int b = blockIdx.x;
    if (b < gw) {
        int idx = b * 256 + threadIdx.x;        // 27*256 fragments
        if (idx == 0) g_tilectr = 0;
        if (idx < 27 * 256) {
            int ac = idx & 3, kt = (idx >> 2) & 1, n = (idx >> 3) & 31, k = idx >> 8;
            int j1 = ac + 8 * kt, j2 = ac + 4 + 8 * kt;
            const float* wp = weight + (size_t)k * 1024 + n;
            float w10 = -__ldg(wp + (2 * j1) * 32);
            float w11 = -__ldg(wp + (2 * j1 + 1) * 32);
            float w20 = -__ldg(wp + (2 * j2) * 32);
            float w21 = -__ldg(wp + (2 * j2 + 1) * 32);
            uint32_t h1, l1, h2, l2;
            split2(w10, w11, h1, l1);
            split2(w20, w21, h2, l2);
            g_b[idx] = make_uint4(h1, h2, l1, l2);
        }
        return;
    }
    if (b < gw + gz) {
        int i = (b - gw) * 256 + threadIdx.x;
        if (i < M) g_cursor[i] = 0;
        return;
    }
    int t = (b - gw - gz) * 256 + threadIdx.x;
    if (t >= n8) return;
    float4 v = feat4[t];
    float4 bb = __ldg(bias4 + (t & 7));
    out4[t] = make_float4(v.x - bb.x, v.y - bb.y, v.z - bb.z, v.w - bb.w);
}

// ---- launch 2: scatter pool pairs into buckets ------------------------------
__global__ void fill_kernel(const int* __restrict__ pin,
                            const int* __restrict__ pout, int P) {
    int p = blockIdx.x * 256 + threadIdx.x;
    if (p < P) {
        int o = __ldg(pout + p);
        int s = atomicAdd(&g_cursor[o], 1);
        g_csr[(size_t)o * 32 + s] = __ldg(pin + p);
    }
}

// ---- launch 3: pooled avg -> interleaved hi/lo bf16 fragment rows -----------
__global__ void pool_gather_kernel(const float4* __restrict__ feat4,
                                   const int* __restrict__ counts, int M) {
    int t = blockIdx.x * 256 + threadIdx.x;
    if (t >= M * 8) return;
    int m = t >> 3, cg = t & 7;
    int cnt = counts[m];
    const int4* row4 = (const int4*)(g_csr + (size_t)m * 32);
    float4 acc = make_float4(0.f, 0.f, 0.f, 0.f);
    for (int eb = 0; eb < cnt; eb += 4) {
        int4 q = __ldg(&row4[eb >> 2]);          // 4 indices, 1 LDG.128
        float4 v0, v1, v2, v3;
        bool m0 = eb + 0 < cnt, m1 = eb + 1 < cnt,
             m2 = eb + 2 < cnt, m3 = eb + 3 < cnt;
        if (m0) v0 = __ldg(&feat4[(size_t)q.x * 8 + cg]);
        if (m1) v1 = __ldg(&feat4[(size_t)q.y * 8 + cg]);
        if (m2) v2 = __ldg(&feat4[(size_t)q.z * 8 + cg]);
        if (m3) v3 = __ldg(&feat4[(size_t)q.w * 8 + cg]);
        if (m0) { acc.x += v0.x; acc.y += v0.y; acc.z += v0.z; acc.w += v0.w; }
        if (m1) { acc.x += v1.x; acc.y += v1.y; acc.z += v1.z; acc.w += v1.w; }
        if (m2) { acc.x += v2.x; acc.y += v2.y; acc.z += v2.z; acc.w += v2.w; }
        if (m3) { acc.x += v3.x; acc.y += v3.y; acc.z += v3.z; acc.w += v3.w; }
    }
    float inv = 1.0f / (float)cnt;
    acc.x *= inv; acc.y *= inv; acc.z *= inv; acc.w *= inv;
    uint32_t h0, l0, h1, l1;
    split2(acc.x, acc.y, h0, l0);   // channel pair p0 = 2*cg
    split2(acc.z, acc.w, h1, l1);   // channel pair p1 = 2*cg+1
    uint32_t* a = (uint32_t*)g_a;
    int p0 = 2 * cg, p1 = 2 * cg + 1;
    size_t base = (size_t)m * 32;
    a[base + (p0 & 3) * 4 + (p0 >> 2)] = h0;
    a[base + (p1 & 3) * 4 + (p1 >> 2)] = h1;
    a[base + 16 + (p0 & 3) * 4 + (p0 >> 2)] = l0;
    a[base + 16 + (p1 & 3) * 4 + (p1 >> 2)] = l1;
}

// ---- launch 4: up pass — work-stealing grains, pipelined, barrier-free ------
__global__ void __launch_bounds__(128, 6)
up_mma_kernel(const int* __restrict__ uin,
              const int* __restrict__ uout,
              const int* __restrict__ uk,
              float* __restrict__ out, int U, int nwt) {
    __shared__ __align__(16) float sred[4][16 * 36];  // per-warp transpose buffer
    int lane = threadIdx.x & 31;
    int w = threadIdx.x >> 5;
    int ar = lane >> 2, ac = lane & 3;
    int lastk = -1;
    uint4 b[4][2];   // (hi0, hi1, lo0, lo1) per [nt][kt]
    float* ss = sred[w];

    for (;;) {
        // ---- steal a grain of GRAIN contiguous tiles ----
        int chunk = 0;
        if (lane == 0) chunk = atomicAdd(&g_tilectr, 1);
        chunk = __shfl_sync(~0u, chunk, 0);
        int wt0 = chunk * GRAIN;
        if (wt0 >= nwt) break;
        int wt1 = min(wt0 + GRAIN, nwt);

        // prologue: load first tile's index triple (lanes 0..15)
        int kv = -1, inv = 0, outv = 0;
        {
            int p = wt0 * 16 + lane;
            if (lane < 16 && p < U) {
                kv = __ldg(uk + p);
                inv = __ldg(uin + p);
                outv = __ldg(uout + p);
            }
        }

        for (int wt = wt0; wt < wt1; wt++) {
            int base = wt * 16;
            // prefetch next tile's triple (overlaps this tile's compute)
            int nkv = -1, ninv = 0, noutv = 0;
            if (wt + 1 < wt1) {
                int p = base + 16 + lane;
                if (lane < 16 && p < U) {
                    nkv = __ldg(uk + p);
                    ninv = __ldg(uin + p);
                    noutv = __ldg(uout + p);
                }
            }
            // uk globally non-decreasing: range = first/last valid lane
            int lastLane = min(15, U - 1 - base);
            int kmn = __shfl_sync(~0u, kv, 0);
            int kmx = __shfl_sync(~0u, kv, lastLane);
            int in0 = __shfl_sync(~0u, inv, ar), in1 = __shfl_sync(~0u, inv, ar + 8);
            int k0  = __shfl_sync(~0u, kv, ar),  k1  = __shfl_sync(~0u, kv, ar + 8);

            float c[4][4];
            #pragma unroll
            for (int i = 0; i < 4; i++)
                #pragma unroll
                for (int j = 0; j < 4; j++) c[i][j] = 0.f;

            for (int k = kmn; k <= kmx; k++) {
                uint4 z = make_uint4(0, 0, 0, 0);
                uint4 Ah0 = (k0 == k) ? __ldg(&g_a[(size_t)in0 * 8 + ac]) : z;
                uint4 Al0 = (k0 == k) ? __ldg(&g_a[(size_t)in0 * 8 + 4 + ac]) : z;
                uint4 Ah1 = (k1 == k) ? __ldg(&g_a[(size_t)in1 * 8 + ac]) : z;
                uint4 Al1 = (k1 == k) ? __ldg(&g_a[(size_t)in1 * 8 + 4 + ac]) : z;
                if (k != lastk) {   // rare: grain tiles are contiguous
                    #pragma unroll
                    for (int nt = 0; nt < 4; nt++)
                        #pragma unroll
                        for (int kt = 0; kt < 2; kt++)
                            b[nt][kt] = __ldg(&g_b[k * 256 + (ar + 8 * nt) * 8 + kt * 4 + ac]);
                    lastk = k;
                }
                #pragma unroll
                for (int nt = 0; nt < 4; nt++) {
                    mma_bf16(c[nt], Ah0.x, Ah1.x, Ah0.y, Ah1.y, b[nt][0].x, b[nt][0].y);
                    mma_bf16(c[nt], Ah0.x, Ah1.x, Ah0.y, Ah1.y, b[nt][0].z, b[nt][0].w);
                    mma_bf16(c[nt], Al0.x, Al1.x, Al0.y, Al1.y, b[nt][0].x, b[nt][0].y);
                    mma_bf16(c[nt], Ah0.z, Ah1.z, Ah0.w, Ah1.w, b[nt][1].x, b[nt][1].y);
                    mma_bf16(c[nt], Ah0.z, Ah1.z, Ah0.w, Ah1.w, b[nt][1].z, b[nt][1].w);
                    mma_bf16(c[nt], Al0.z, Al1.z, Al0.w, Al1.w, b[nt][1].x, b[nt][1].y);
                }
            }
            // ---- epilogue: warp-private SMEM transpose -> full-row v4 REDs ----
            #pragma unroll
            for (int nt = 0; nt < 4; nt++) {
                int col = nt * 8 + 2 * ac;
                *(float2*)&ss[ar * 36 + col]       = make_float2(c[nt][0], c[nt][1]);
                *(float2*)&ss[(ar + 8) * 36 + col] = make_float2(c[nt][2], c[nt][3]);
            }
            __syncwarp();
            int ch = (lane & 7) * 4;
            #pragma unroll
            for (int i = 0; i < 4; i++) {
                int r = i * 4 + (lane >> 3);
                int orow = __shfl_sync(~0u, outv, r);
                float4 v = *(float4*)&ss[r * 36 + ch];
                if (base + r < U)
                    red_add_v4(out + (size_t)orow * 32 + ch, v.x, v.y, v.z, v.w);
            }
            __syncwarp();
            kv = nkv; inv = ninv; outv = noutv;
        }
    }
}

// ------------------------------------ launch --------------------------------
extern "C" void kernel_launch(void* const* d_in, const int* in_sizes, int n_in,
                              void* d_out, int out_size) {
    const float* feat   = (const float*)d_in[0];
    const float* weight = (const float*)d_in[1];
    const float* bias   = (const float*)d_in[2];
    const int* pin      = (const int*)d_in[3];
    const int* pout     = (const int*)d_in[4];
    const int* counts   = (const int*)d_in[5];
    const int* uin      = (const int*)d_in[6];
    const int* uout     = (const int*)d_in[7];
    const int* uk       = (const int*)d_in[8];
    float* out          = (float*)d_out;

    int P = in_sizes[3];
    int M = in_sizes[5];
    int U = in_sizes[6];
    int n8 = out_size / 4;

    int gw = 27;
    int gz = (M + 255) / 256;
    int gi = (n8 + 255) / 256;
    prep_kernel<<<gw + gz + gi, 256>>>(weight, (const float4*)feat,
                                       (const float4*)bias, (float4*)out,
                                       M, n8, gw, gz);
    fill_kernel<<<(P + 255) / 256, 256>>>(pin, pout, P);
    pool_gather_kernel<<<(M * 8 + 255) / 256, 256>>>((const float4*)feat, counts, M);

    int nwt = (U + 15) / 16;
    up_mma_kernel<<<888, 128>>>(uin, uout, uk, out, U, nwt);
}

// round 12
// speedup vs baseline: 1.1196x; 1.1196x over previous
#include <cuda_runtime.h>
#include <cstdint>

// ---------------------------------------------------------------------------
// Round 12:
//   up: REVERT to round-9 (static contiguous chunks, grid 1776, no prefetch —
//       rounds 10/11 isolated the prefetch pipeline as the regression), plus
//       sorted-k range shortcut (uk globally non-decreasing) replacing the
//       butterfly reduce.
//   pool_gather: 8-wide gather batches (2x int4 index quads) for 2x MLP.
// ---------------------------------------------------------------------------

__device__ uint4 g_a[1000000 * 8];    // pooled rows: [m][0..3]=hi frags, [4..7]=lo
__device__ uint4 g_b[27 * 256];       // -W fragments: (h1,h2,l1,l2)
__device__ int   g_cursor[1000000];
__device__ __align__(16) int g_csr[32000000];   // 32-slot buckets per pooled row

static __device__ __forceinline__ void red_add_v4(float* dst, float a, float b,
                                                  float c, float d) {
    asm volatile("red.global.add.v4.f32 [%0], {%1,%2,%3,%4};"
                 :: "l"(dst), "f"(a), "f"(b), "f"(c), "f"(d) : "memory");
}
static __device__ __forceinline__ uint32_t bf2(float hi, float lo) {
    uint32_t r;
    asm("cvt.rn.bf16x2.f32 %0, %1, %2;" : "=r"(r) : "f"(hi), "f"(lo));
    return r;
}
static __device__ __forceinline__ void split2(float v0, float v1,
                                              uint32_t& h, uint32_t& l) {
    h = bf2(v1, v0);
    float f0 = __uint_as_float(h << 16);
    float f1 = __uint_as_float(h & 0xFFFF0000u);
    l = bf2(v1 - f1, v0 - f0);
}
static __device__ __forceinline__ void mma_bf16(float c[4],
        uint32_t a0, uint32_t a1, uint32_t a2, uint32_t a3,
        uint32_t b0, uint32_t b1) {
    asm volatile(
        "mma.sync.aligned.m16n8k16.row.col.f32.bf16.bf16.f32 "
        "{%0,%1,%2,%3}, {%4,%5,%6,%7}, {%8,%9}, {%0,%1,%2,%3};"
        : "+f"(c[0]), "+f"(c[1]), "+f"(c[2]), "+f"(c[3])
        : "r"(a0), "r"(a1), "r"(a2), "r"(a3), "r"(b0), "r"(b1));
}

// ---- launch 1: weight-split + zero cursors + out = feat - bias (fused) -----
__global__ void prep_kernel(const float* __restrict__ weight,
                            const float4* __restrict__ feat4,
                            const float4* __restrict__ bias4,
                            float4* __restrict__ out4,
                            int M, int n8, int gw, int gz) {
    int b = blockIdx.x;
    if (b < gw) {
        int idx = b * 256 + threadIdx.x;        // 27*256 fragments
        if (idx < 27 * 256) {
            int ac = idx & 3, kt = (idx >> 2) & 1, n = (idx >> 3) & 31, k = idx >> 8;
            int j1 = ac + 8 * kt, j2 = ac + 4 + 8 * kt;
            const float* wp = weight + (size_t)k * 1024 + n;
            float w10 = -__ldg(wp + (2 * j1) * 32);
            float w11 = -__ldg(wp + (2 * j1 + 1) * 32);
            float w20 = -__ldg(wp + (2 * j2) * 32);
            float w21 = -__ldg(wp + (2 * j2 + 1) * 32);
            uint32_t h1, l1, h2, l2;
            split2(w10, w11, h1, l1);
            split2(w20, w21, h2, l2);
            g_b[idx] = make_uint4(h1, h2, l1, l2);
        }
        return;
    }
    if (b < gw + gz) {
        int i = (b - gw) * 256 + threadIdx.x;
        if (i < M) g_cursor[i] = 0;
        return;
    }
    int t = (b - gw - gz) * 256 + threadIdx.x;
    if (t >= n8) return;
    float4 v = feat4[t];
    float4 bb = __ldg(bias4 + (t & 7));
    out4[t] = make_float4(v.x - bb.x, v.y - bb.y, v.z - bb.z, v.w - bb.w);
}

// ---- launch 2: scatter pool pairs into buckets ------------------------------
__global__ void fill_kernel(const int* __restrict__ pin,
                            const int* __restrict__ pout, int P) {
    int p = blockIdx.x * 256 + threadIdx.x;
    if (p < P) {
        int o = __ldg(pout + p);
        int s = atomicAdd(&g_cursor[o], 1);
        g_csr[(size_t)o * 32 + s] = __ldg(pin + p);
    }
}

// ---- launch 3: pooled avg -> interleaved hi/lo bf16 fragment rows -----------
__global__ void pool_gather_kernel(const float4* __restrict__ feat4,
                                   const int* __restrict__ counts, int M) {
    int t = blockIdx.x * 256 + threadIdx.x;
    if (t >= M * 8) return;
    int m = t >> 3, cg = t & 7;
    int cnt = counts[m];
    const int4* row4 = (const int4*)(g_csr + (size_t)m * 32);
    float4 acc = make_float4(0.f, 0.f, 0.f, 0.f);
    for (int eb = 0; eb < cnt; eb += 8) {
        // load both index quads up front, issue up to 8 gathers together
        int4 qa = __ldg(&row4[eb >> 2]);
        int4 qb = (eb + 4 < cnt) ? __ldg(&row4[(eb >> 2) + 1]) : make_int4(0, 0, 0, 0);
        int idxs[8] = {qa.x, qa.y, qa.z, qa.w, qb.x, qb.y, qb.z, qb.w};
        float4 v[8];
        #pragma unroll
        for (int j = 0; j < 8; j++)
            if (eb + j < cnt) v[j] = __ldg(&feat4[(size_t)idxs[j] * 8 + cg]);
        #pragma unroll
        for (int j = 0; j < 8; j++)
            if (eb + j < cnt) {
                acc.x += v[j].x; acc.y += v[j].y;
                acc.z += v[j].z; acc.w += v[j].w;
            }
    }
    float inv = 1.0f / (float)cnt;
    acc.x *= inv; acc.y *= inv; acc.z *= inv; acc.w *= inv;
    uint32_t h0, l0, h1, l1;
    split2(acc.x, acc.y, h0, l0);   // channel pair p0 = 2*cg
    split2(acc.z, acc.w, h1, l1);   // channel pair p1 = 2*cg+1
    uint32_t* a = (uint32_t*)g_a;
    int p0 = 2 * cg, p1 = 2 * cg + 1;
    size_t base = (size_t)m * 32;
    a[base + (p0 & 3) * 4 + (p0 >> 2)] = h0;
    a[base + (p1 & 3) * 4 + (p1 >> 2)] = h1;
    a[base + 16 + (p0 & 3) * 4 + (p0 >> 2)] = l0;
    a[base + 16 + (p1 & 3) * 4 + (p1 >> 2)] = l1;
}

// ---- launch 4: up pass — round-9 structure + sorted-k shortcut ---------------
__global__ void __launch_bounds__(128, 6)
up_mma_kernel(const int* __restrict__ uin,
              const int* __restrict__ uout,
              const int* __restrict__ uk,
              float* __restrict__ out, int U, int nwt, int cpw) {
    __shared__ __align__(16) float sred[4][16 * 36];  // per-warp transpose buffer
    int lane = threadIdx.x & 31;
    int w = threadIdx.x >> 5;
    int ar = lane >> 2, ac = lane & 3;
    int wg = blockIdx.x * 4 + w;
    int wt0 = wg * cpw;
    int wt1 = min(wt0 + cpw, nwt);
    int lastk = -1;
    uint4 b[4][2];   // (hi0, hi1, lo0, lo1) per [nt][kt]
    float* ss = sred[w];

    for (int wt = wt0; wt < wt1; wt++) {
        int base = wt * 16;
        int p = base + lane;
        int kv = -1, inv = 0, outv = 0;
        if (lane < 16 && p < U) {
            kv = __ldg(uk + p);
            inv = __ldg(uin + p);
            outv = __ldg(uout + p);
        }
        // uk globally non-decreasing: range = first / last valid lane
        int lastLane = min(15, U - 1 - base);
        int kmn = __shfl_sync(~0u, kv, 0);
        int kmx = __shfl_sync(~0u, kv, lastLane);
        int in0 = __shfl_sync(~0u, inv, ar), in1 = __shfl_sync(~0u, inv, ar + 8);
        int k0  = __shfl_sync(~0u, kv, ar),  k1  = __shfl_sync(~0u, kv, ar + 8);

        float c[4][4];
        #pragma unroll
        for (int i = 0; i < 4; i++)
            #pragma unroll
            for (int j = 0; j < 4; j++) c[i][j] = 0.f;

        for (int k = kmn; k <= kmx; k++) {
            if (k != lastk) {   // rare: tiles are contiguous in pair space
                #pragma unroll
                for (int nt = 0; nt < 4; nt++)
                    #pragma unroll
                    for (int kt = 0; kt < 2; kt++)
                        b[nt][kt] = __ldg(&g_b[k * 256 + (ar + 8 * nt) * 8 + kt * 4 + ac]);
                lastk = k;
            }
            uint4 z = make_uint4(0, 0, 0, 0);
            uint4 Ah0 = (k0 == k) ? __ldg(&g_a[(size_t)in0 * 8 + ac]) : z;
            uint4 Al0 = (k0 == k) ? __ldg(&g_a[(size_t)in0 * 8 + 4 + ac]) : z;
            uint4 Ah1 = (k1 == k) ? __ldg(&g_a[(size_t)in1 * 8 + ac]) : z;
            uint4 Al1 = (k1 == k) ? __ldg(&g_a[(size_t)in1 * 8 + 4 + ac]) : z;
            #pragma unroll
            for (int nt = 0; nt < 4; nt++) {
                mma_bf16(c[nt], Ah0.x, Ah1.x, Ah0.y, Ah1.y, b[nt][0].x, b[nt][0].y);
                mma_bf16(c[nt], Ah0.x, Ah1.x, Ah0.y, Ah1.y, b[nt][0].z, b[nt][0].w);
                mma_bf16(c[nt], Al0.x, Al1.x, Al0.y, Al1.y, b[nt][0].x, b[nt][0].y);
                mma_bf16(c[nt], Ah0.z, Ah1.z, Ah0.w, Ah1.w, b[nt][1].x, b[nt][1].y);
                mma_bf16(c[nt], Ah0.z, Ah1.z, Ah0.w, Ah1.w, b[nt][1].z, b[nt][1].w);
                mma_bf16(c[nt], Al0.z, Al1.z, Al0.w, Al1.w, b[nt][1].x, b[nt][1].y);
            }
        }
        // ---- epilogue: warp-private SMEM transpose -> full-row v4 REDs ----
        #pragma unroll
        for (int nt = 0; nt < 4; nt++) {
            int col = nt * 8 + 2 * ac;
            *(float2*)&ss[ar * 36 + col]       = make_float2(c[nt][0], c[nt][1]);
            *(float2*)&ss[(ar + 8) * 36 + col] = make_float2(c[nt][2], c[nt][3]);
        }
        __syncwarp();
        int ch = (lane & 7) * 4;
        #pragma unroll
        for (int i = 0; i < 4; i++) {
            int r = i * 4 + (lane >> 3);
            int orow = __shfl_sync(~0u, outv, r);
            float4 v = *(float4*)&ss[r * 36 + ch];
            if (base + r < U)
                red_add_v4(out + (size_t)orow * 32 + ch, v.x, v.y, v.z, v.w);
        }
        __syncwarp();
    }
}

// ------------------------------------ launch --------------------------------
extern "C" void kernel_launch(void* const* d_in, const int* in_sizes, int n_in,
                              void* d_out, int out_size) {
    const float* feat   = (const float*)d_in[0];
    const float* weight = (const float*)d_in[1];
    const float* bias   = (const float*)d_in[2];
    const int* pin      = (const int*)d_in[3];
    const int* pout     = (const int*)d_in[4];
    const int* counts   = (const int*)d_in[5];
    const int* uin      = (const int*)d_in[6];
    const int* uout     = (const int*)d_in[7];
    const int* uk       = (const int*)d_in[8];
    float* out          = (float*)d_out;

    int P = in_sizes[3];
    int M = in_sizes[5];
    int U = in_sizes[6];
    int n8 = out_size / 4;

    int gw = 27;
    int gz = (M + 255) / 256;
    int gi = (n8 + 255) / 256;
    prep_kernel<<<gw + gz + gi, 256>>>(weight, (const float4*)feat,
                                       (const float4*)bias, (float4*)out,
                                       M, n8, gw, gz);
    fill_kernel<<<(P + 255) / 256, 256>>>(pin, pout, P);
    pool_gather_kernel<<<(M * 8 + 255) / 256, 256>>>((const float4*)feat, counts, M);

    int nwt = (U + 15) / 16;
    int grid = 1776;
    int nwarps = grid * 4;
    int cpw = (nwt + nwarps - 1) / nwarps;   // contiguous tiles per warp
    up_mma_kernel<<<grid, 128>>>(uin, uout, uk, out, U, nwt, cpw);
}